// round 7
// baseline (speedup 1.0000x reference)
#include <cuda_runtime.h>
#include <math.h>

#define C 128
#define CV 32          // C/4 float4 per row
#define HID 8
#define NB 16
#define RED_BLOCKS 1184   // 8 blocks/SM: full 64-warp occupancy
#define APPLY_BLOCKS 1184

// Scratch (no allocations allowed). Zero-initialized at load; the fused MLP
// tail re-zeroes g_sums/g_counts/g_done after consuming, so every call
// (correctness, capture, replay) starts from zeros. Deterministic.
__device__ float g_sums[NB][C];
__device__ float g_counts[NB];
__device__ float g_gate[NB][C];
__device__ unsigned int g_done;

// ---------------------------------------------------------------------------
// 1) segment sum + fused MLP tail.
//    Block owns contiguous rows [row0,row1); bidx sorted, 16 segments ->
//    block spans few segments; binary-search boundaries, then stream each
//    segment with a pure load/FADD loop (unroll 8, two accumulators).
//    The LAST block to finish computes the tiny SE MLP in-place.
// ---------------------------------------------------------------------------
__device__ __forceinline__ int lower_bound_idx(const int* __restrict__ bidx,
                                               int lo, int hi, int val) {
    while (lo < hi) {
        int mid = (lo + hi) >> 1;
        if (bidx[mid] < val) lo = mid + 1; else hi = mid;
    }
    return lo;
}

__global__ __launch_bounds__(256) void reduce_mlp_kernel(
    const float4* __restrict__ x, const int* __restrict__ bidx,
    int n, int rows_per_block,
    const float* __restrict__ W1, const float* __restrict__ b1,
    const float* __restrict__ W2, const float* __restrict__ b2)
{
    int row0 = blockIdx.x * rows_per_block;
    int row1 = row0 + rows_per_block;
    if (row1 > n) row1 = n;

    int warp = threadIdx.x >> 5;
    int lane = threadIdx.x & 31;

    if (row0 < row1) {
        int b_first = bidx[row0];
        int b_last  = bidx[row1 - 1];

        int seg_start = row0;
        for (int b = b_first; b <= b_last; b++) {
            int seg_end = (b == b_last) ? row1
                        : lower_bound_idx(bidx, seg_start, row1, b + 1);

            float4 accA = make_float4(0.f, 0.f, 0.f, 0.f);
            float4 accB = make_float4(0.f, 0.f, 0.f, 0.f);

            int r = seg_start + warp;
            for (; r + 56 < seg_end; r += 64) {
                float4 v0 = x[(size_t)(r)      * CV + lane];
                float4 v1 = x[(size_t)(r + 8)  * CV + lane];
                float4 v2 = x[(size_t)(r + 16) * CV + lane];
                float4 v3 = x[(size_t)(r + 24) * CV + lane];
                float4 v4 = x[(size_t)(r + 32) * CV + lane];
                float4 v5 = x[(size_t)(r + 40) * CV + lane];
                float4 v6 = x[(size_t)(r + 48) * CV + lane];
                float4 v7 = x[(size_t)(r + 56) * CV + lane];
                accA.x += v0.x; accA.y += v0.y; accA.z += v0.z; accA.w += v0.w;
                accB.x += v1.x; accB.y += v1.y; accB.z += v1.z; accB.w += v1.w;
                accA.x += v2.x; accA.y += v2.y; accA.z += v2.z; accA.w += v2.w;
                accB.x += v3.x; accB.y += v3.y; accB.z += v3.z; accB.w += v3.w;
                accA.x += v4.x; accA.y += v4.y; accA.z += v4.z; accA.w += v4.w;
                accB.x += v5.x; accB.y += v5.y; accB.z += v5.z; accB.w += v5.w;
                accA.x += v6.x; accA.y += v6.y; accA.z += v6.z; accA.w += v6.w;
                accB.x += v7.x; accB.y += v7.y; accB.z += v7.z; accB.w += v7.w;
            }
            for (; r < seg_end; r += 8) {
                float4 v = x[(size_t)r * CV + lane];
                accA.x += v.x; accA.y += v.y; accA.z += v.z; accA.w += v.w;
            }

            int seg_len = seg_end - seg_start;
            if (seg_len > 0) {
                float* dst = &g_sums[b][lane * 4];
                atomicAdd(dst + 0, accA.x + accB.x);
                atomicAdd(dst + 1, accA.y + accB.y);
                atomicAdd(dst + 2, accA.z + accB.z);
                atomicAdd(dst + 3, accA.w + accB.w);
                if (lane == 0 && warp == 0)
                    atomicAdd(&g_counts[b], (float)seg_len);
            }
            seg_start = seg_end;
        }
    }

    // ---- last-block-done MLP tail ----
    __shared__ unsigned int s_is_last;
    __threadfence();                 // publish this block's atomics
    __syncthreads();
    if (threadIdx.x == 0) {
        unsigned int old = atomicAdd(&g_done, 1u);
        s_is_last = (old == (unsigned int)gridDim.x - 1u) ? 1u : 0u;
    }
    __syncthreads();
    if (!s_is_last) return;

    __threadfence();                 // acquire side: see all blocks' sums

    __shared__ float s_mean[NB][C];
    __shared__ float s_h[NB][HID];
    int t = threadIdx.x;             // 0..255

    for (int i = t; i < NB * C; i += 256) {
        int b = i / C, c = i % C;
        float cn = fmaxf(g_counts[b], 1.0f);
        s_mean[b][c] = g_sums[b][c] / cn;
    }
    __syncthreads();

    // reset state for the next invocation
    for (int i = t; i < NB * C; i += 256) ((float*)g_sums)[i] = 0.0f;
    if (t < NB) g_counts[t] = 0.0f;
    if (t == 0) g_done = 0u;

    if (t < NB * HID) {              // 128 outputs: h[b][j]
        int b = t / HID, j = t % HID;
        float acc = b1[j];
        #pragma unroll 8
        for (int c = 0; c < C; c++) acc += s_mean[b][c] * W1[c * HID + j];
        s_h[b][j] = fmaxf(acc, 0.0f);
    }
    __syncthreads();

    if (t < C) {                     // gate column c = t
        int c = t;
        float w2c[HID];
        #pragma unroll
        for (int j = 0; j < HID; j++) w2c[j] = W2[j * C + c];
        float bias = b2[c];
        for (int b = 0; b < NB; b++) {
            float acc = bias;
            #pragma unroll
            for (int j = 0; j < HID; j++) acc += s_h[b][j] * w2c[j];
            g_gate[b][c] = 1.0f / (1.0f + expf(-acc));
        }
    }
}

// ---------------------------------------------------------------------------
// 2) apply gate: out[r][c] = x[r][c] * gate[bidx[r]][c]   (512 MB traffic)
//    R4 form (measured 77 us): grid-stride, ascending, plain loads/stores,
//    x2 unroll with front-batched loads.
// ---------------------------------------------------------------------------
__global__ __launch_bounds__(256) void apply_kernel(
    const float4* __restrict__ x, const int* __restrict__ bidx,
    float4* __restrict__ out, int n)
{
    __shared__ float4 s_gate[NB][CV];  // 8 KB
    for (int i = threadIdx.x; i < NB * CV; i += blockDim.x)
        ((float4*)s_gate)[i] = ((const float4*)g_gate)[i];
    __syncthreads();

    int lane = threadIdx.x & 31;
    int gwarp = (blockIdx.x * blockDim.x + threadIdx.x) >> 5;
    int nwarps = (gridDim.x * blockDim.x) >> 5;

    int r = gwarp;
    for (; r + nwarps < n; r += 2 * nwarps) {
        int r2 = r + nwarps;
        int b0 = bidx[r];
        int b1 = bidx[r2];
        float4 v0 = x[(size_t)r  * CV + lane];
        float4 v1 = x[(size_t)r2 * CV + lane];
        float4 g0 = s_gate[b0][lane];
        float4 g1 = s_gate[b1][lane];
        v0.x *= g0.x; v0.y *= g0.y; v0.z *= g0.z; v0.w *= g0.w;
        v1.x *= g1.x; v1.y *= g1.y; v1.z *= g1.z; v1.w *= g1.w;
        out[(size_t)r  * CV + lane] = v0;
        out[(size_t)r2 * CV + lane] = v1;
    }
    if (r < n) {
        int b = bidx[r];
        float4 v = x[(size_t)r * CV + lane];
        float4 g = s_gate[b][lane];
        v.x *= g.x; v.y *= g.y; v.z *= g.z; v.w *= g.w;
        out[(size_t)r * CV + lane] = v;
    }
}

// ---------------------------------------------------------------------------
extern "C" void kernel_launch(void* const* d_in, const int* in_sizes, int n_in,
                              void* d_out, int out_size)
{
    const float* x    = (const float*)d_in[0];
    const int*   bidx = (const int*)d_in[1];
    const float* W1   = (const float*)d_in[2];
    const float* b1   = (const float*)d_in[3];
    const float* W2   = (const float*)d_in[4];
    const float* b2   = (const float*)d_in[5];
    float* out = (float*)d_out;

    int n = in_sizes[1];  // number of rows (batch_idx has N entries)
    int rows_per_block = (n + RED_BLOCKS - 1) / RED_BLOCKS;

    reduce_mlp_kernel<<<RED_BLOCKS, 256>>>((const float4*)x, bidx, n,
                                           rows_per_block, W1, b1, W2, b2);
    apply_kernel<<<APPLY_BLOCKS, 256>>>((const float4*)x, bidx, (float4*)out, n);
}

// round 8
// speedup vs baseline: 1.1312x; 1.1312x over previous
#include <cuda_runtime.h>
#include <math.h>

#define C 128
#define CV 32          // C/4 float4 per row
#define HID 8
#define NB 16
#define RED_BLOCKS 888    // 6 blocks/SM x 148 SMs: single full wave at ~38 regs
#define APPLY_BLOCKS 1184

// Scratch (no allocations allowed). Zero-initialized at load; mlp_kernel
// re-zeroes g_sums/g_counts after consuming them, so every call
// (correctness, capture, replay) starts from zeros. Deterministic.
__device__ float g_sums[NB][C];
__device__ float g_counts[NB];
__device__ float g_gate[NB][C];

// ---------------------------------------------------------------------------
// 1) segment sum. Block owns contiguous rows [row0,row1); bidx sorted, 16
//    segments -> block spans few segments; binary-search boundaries, then
//    stream each segment with a pure load/FADD loop (unroll 8, 2 accums).
// ---------------------------------------------------------------------------
__device__ __forceinline__ int lower_bound_idx(const int* __restrict__ bidx,
                                               int lo, int hi, int val) {
    while (lo < hi) {
        int mid = (lo + hi) >> 1;
        if (bidx[mid] < val) lo = mid + 1; else hi = mid;
    }
    return lo;
}

__global__ __launch_bounds__(256) void reduce_kernel(
    const float4* __restrict__ x, const int* __restrict__ bidx,
    int n, int rows_per_block)
{
    int row0 = blockIdx.x * rows_per_block;
    int row1 = row0 + rows_per_block;
    if (row1 > n) row1 = n;
    if (row0 >= row1) return;

    int warp = threadIdx.x >> 5;
    int lane = threadIdx.x & 31;

    int b_first = bidx[row0];
    int b_last  = bidx[row1 - 1];

    int seg_start = row0;
    for (int b = b_first; b <= b_last; b++) {
        int seg_end = (b == b_last) ? row1
                    : lower_bound_idx(bidx, seg_start, row1, b + 1);

        float4 accA = make_float4(0.f, 0.f, 0.f, 0.f);
        float4 accB = make_float4(0.f, 0.f, 0.f, 0.f);

        int r = seg_start + warp;
        for (; r + 56 < seg_end; r += 64) {
            float4 v0 = x[(size_t)(r)      * CV + lane];
            float4 v1 = x[(size_t)(r + 8)  * CV + lane];
            float4 v2 = x[(size_t)(r + 16) * CV + lane];
            float4 v3 = x[(size_t)(r + 24) * CV + lane];
            float4 v4 = x[(size_t)(r + 32) * CV + lane];
            float4 v5 = x[(size_t)(r + 40) * CV + lane];
            float4 v6 = x[(size_t)(r + 48) * CV + lane];
            float4 v7 = x[(size_t)(r + 56) * CV + lane];
            accA.x += v0.x; accA.y += v0.y; accA.z += v0.z; accA.w += v0.w;
            accB.x += v1.x; accB.y += v1.y; accB.z += v1.z; accB.w += v1.w;
            accA.x += v2.x; accA.y += v2.y; accA.z += v2.z; accA.w += v2.w;
            accB.x += v3.x; accB.y += v3.y; accB.z += v3.z; accB.w += v3.w;
            accA.x += v4.x; accA.y += v4.y; accA.z += v4.z; accA.w += v4.w;
            accB.x += v5.x; accB.y += v5.y; accB.z += v5.z; accB.w += v5.w;
            accA.x += v6.x; accA.y += v6.y; accA.z += v6.z; accA.w += v6.w;
            accB.x += v7.x; accB.y += v7.y; accB.z += v7.z; accB.w += v7.w;
        }
        for (; r < seg_end; r += 8) {
            float4 v = x[(size_t)r * CV + lane];
            accA.x += v.x; accA.y += v.y; accA.z += v.z; accA.w += v.w;
        }

        int seg_len = seg_end - seg_start;
        if (seg_len > 0) {
            float* dst = &g_sums[b][lane * 4];
            atomicAdd(dst + 0, accA.x + accB.x);
            atomicAdd(dst + 1, accA.y + accB.y);
            atomicAdd(dst + 2, accA.z + accB.z);
            atomicAdd(dst + 3, accA.w + accB.w);
            if (lane == 0 && warp == 0)
                atomicAdd(&g_counts[b], (float)seg_len);
        }
        seg_start = seg_end;
    }
}

// ---------------------------------------------------------------------------
// 2) tiny MLP: mean -> Linear(128,8) -> ReLU -> Linear(8,128) -> sigmoid.
//    Re-zeroes g_sums/g_counts for the next call.
// ---------------------------------------------------------------------------
__global__ __launch_bounds__(128) void mlp_kernel(
    const float* __restrict__ W1, const float* __restrict__ b1,
    const float* __restrict__ W2, const float* __restrict__ b2)
{
    __shared__ float s_mean[NB][C];
    __shared__ float s_h[NB][HID];

    int t = threadIdx.x;  // 0..127

    for (int i = t; i < NB * C; i += 128) {
        int b = i / C, c = i % C;
        float cn = fmaxf(g_counts[b], 1.0f);
        s_mean[b][c] = g_sums[b][c] / cn;
    }
    __syncthreads();

    // reset accumulators for the next invocation
    for (int i = t; i < NB * C; i += 128) ((float*)g_sums)[i] = 0.0f;
    if (t < NB) g_counts[t] = 0.0f;

    {
        int b = t / HID, j = t % HID;
        float acc = b1[j];
        #pragma unroll 8
        for (int c = 0; c < C; c++) acc += s_mean[b][c] * W1[c * HID + j];
        s_h[b][j] = fmaxf(acc, 0.0f);
    }
    __syncthreads();

    {
        int c = t;
        float w2c[HID];
        #pragma unroll
        for (int j = 0; j < HID; j++) w2c[j] = W2[j * C + c];
        float bias = b2[c];
        for (int b = 0; b < NB; b++) {
            float acc = bias;
            #pragma unroll
            for (int j = 0; j < HID; j++) acc += s_h[b][j] * w2c[j];
            g_gate[b][c] = 1.0f / (1.0f + expf(-acc));
        }
    }
}

// ---------------------------------------------------------------------------
// 3) apply gate: out[r][c] = x[r][c] * gate[bidx[r]][c]   (512 MB traffic)
//    Grid-stride ascending, plain loads/stores, x2 unroll (measured 78.8us).
// ---------------------------------------------------------------------------
__global__ __launch_bounds__(256) void apply_kernel(
    const float4* __restrict__ x, const int* __restrict__ bidx,
    float4* __restrict__ out, int n)
{
    __shared__ float4 s_gate[NB][CV];  // 8 KB
    for (int i = threadIdx.x; i < NB * CV; i += blockDim.x)
        ((float4*)s_gate)[i] = ((const float4*)g_gate)[i];
    __syncthreads();

    int lane = threadIdx.x & 31;
    int gwarp = (blockIdx.x * blockDim.x + threadIdx.x) >> 5;
    int nwarps = (gridDim.x * blockDim.x) >> 5;

    int r = gwarp;
    for (; r + nwarps < n; r += 2 * nwarps) {
        int r2 = r + nwarps;
        int b0 = bidx[r];
        int b1 = bidx[r2];
        float4 v0 = x[(size_t)r  * CV + lane];
        float4 v1 = x[(size_t)r2 * CV + lane];
        float4 g0 = s_gate[b0][lane];
        float4 g1 = s_gate[b1][lane];
        v0.x *= g0.x; v0.y *= g0.y; v0.z *= g0.z; v0.w *= g0.w;
        v1.x *= g1.x; v1.y *= g1.y; v1.z *= g1.z; v1.w *= g1.w;
        out[(size_t)r  * CV + lane] = v0;
        out[(size_t)r2 * CV + lane] = v1;
    }
    if (r < n) {
        int b = bidx[r];
        float4 v = x[(size_t)r * CV + lane];
        float4 g = s_gate[b][lane];
        v.x *= g.x; v.y *= g.y; v.z *= g.z; v.w *= g.w;
        out[(size_t)r * CV + lane] = v;
    }
}

// ---------------------------------------------------------------------------
extern "C" void kernel_launch(void* const* d_in, const int* in_sizes, int n_in,
                              void* d_out, int out_size)
{
    const float* x    = (const float*)d_in[0];
    const int*   bidx = (const int*)d_in[1];
    const float* W1   = (const float*)d_in[2];
    const float* b1   = (const float*)d_in[3];
    const float* W2   = (const float*)d_in[4];
    const float* b2   = (const float*)d_in[5];
    float* out = (float*)d_out;

    int n = in_sizes[1];  // number of rows (batch_idx has N entries)
    int rows_per_block = (n + RED_BLOCKS - 1) / RED_BLOCKS;

    reduce_kernel<<<RED_BLOCKS, 256>>>((const float4*)x, bidx, n, rows_per_block);
    mlp_kernel<<<1, 128>>>(W1, b1, W2, b2);
    apply_kernel<<<APPLY_BLOCKS, 256>>>((const float4*)x, bidx, (float4*)out, n);
}

// round 9
// speedup vs baseline: 1.1942x; 1.0557x over previous
#include <cuda_runtime.h>
#include <math.h>

#define C 128
#define CV 32            // C/4 float4 per row
#define HID 8
#define NB 16

#define RED_BLOCKS 296   // 2 blocks/SM x 148 SMs (smem-limited)
#define TILE_ROWS 64
#define TILE_F4   (TILE_ROWS * CV)        // float4 per tile
#define TILE_BYTES (TILE_ROWS * C * 4)    // 32768
#define STAGES 3
#define RED_SMEM (STAGES * TILE_BYTES)    // 96 KB dynamic

#define APPLY_BLOCKS 1184

// Scratch (no allocations allowed). Zero-initialized at load; mlp_kernel
// re-zeroes g_sums/g_counts after consuming them -> every call starts clean.
__device__ float g_sums[NB][C];
__device__ float g_counts[NB];
__device__ float g_gate[NB][C];

// ---------------- mbarrier helpers ----------------
__device__ __forceinline__ unsigned smem_u32(const void* p) {
    return (unsigned)__cvta_generic_to_shared(p);
}
__device__ __forceinline__ void mbar_init(unsigned mb, unsigned count) {
    asm volatile("mbarrier.init.shared.b64 [%0], %1;" :: "r"(mb), "r"(count) : "memory");
}
__device__ __forceinline__ void mbar_expect_tx(unsigned mb, unsigned bytes) {
    asm volatile("mbarrier.arrive.expect_tx.shared.b64 _, [%0], %1;"
                 :: "r"(mb), "r"(bytes) : "memory");
}
__device__ __forceinline__ void mbar_wait(unsigned mb, unsigned parity) {
    asm volatile(
        "{\n\t.reg .pred P;\n\t"
        "WAIT_%=:\n\t"
        "mbarrier.try_wait.parity.acquire.cta.shared::cta.b64 P, [%0], %1, 0x989680;\n\t"
        "@!P bra WAIT_%=;\n\t}"
        :: "r"(mb), "r"(parity) : "memory");
}
__device__ __forceinline__ void bulk_ld(unsigned dst_smem, const void* src, unsigned bytes,
                                        unsigned mb) {
    asm volatile(
        "cp.async.bulk.shared::cta.global.mbarrier::complete_tx::bytes [%0], [%1], %2, [%3];"
        :: "r"(dst_smem), "l"(src), "r"(bytes), "r"(mb) : "memory");
}

__device__ __forceinline__ int lower_bound_idx(const int* __restrict__ bidx,
                                               int lo, int hi, int val) {
    while (lo < hi) {
        int mid = (lo + hi) >> 1;
        if (bidx[mid] < val) lo = mid + 1; else hi = mid;
    }
    return lo;
}

// ---------------------------------------------------------------------------
// 1) segment sum via TMA bulk pipeline: one elected thread streams 32KB tiles
//    into a 3-deep SMEM ring; 8 warps consume from SMEM (LDS.128 + FADD).
//    DRAM side is driven by the TMA engine -> not limited by LDG scoreboards.
// ---------------------------------------------------------------------------
__global__ __launch_bounds__(256) void reduce_kernel(
    const float* __restrict__ x, const int* __restrict__ bidx,
    int n, int rows_per_block)
{
    extern __shared__ __align__(128) float4 s_buf[];   // STAGES * TILE_F4
    __shared__ unsigned long long s_mbar_store[STAGES];

    int tid  = threadIdx.x;
    int warp = tid >> 5;
    int lane = tid & 31;

    int row0 = blockIdx.x * rows_per_block;
    int row1 = row0 + rows_per_block;
    if (row1 > n) row1 = n;
    if (row0 >= row1) return;
    int ntiles = (row1 - row0 + TILE_ROWS - 1) / TILE_ROWS;

    unsigned mb[STAGES];
    #pragma unroll
    for (int s = 0; s < STAGES; s++) mb[s] = smem_u32(&s_mbar_store[s]);

    if (tid == 0) {
        #pragma unroll
        for (int s = 0; s < STAGES; s++) mbar_init(mb[s], 1);
        // counts: per-segment overlap of this block (cheap binary searches)
        int bf = bidx[row0], bl = bidx[row1 - 1];
        int s0 = row0;
        for (int b = bf; b <= bl; b++) {
            int e = (b == bl) ? row1 : lower_bound_idx(bidx, s0, row1, b + 1);
            atomicAdd(&g_counts[b], (float)(e - s0));
            s0 = e;
        }
    }
    __syncthreads();

    // prologue: fill the pipeline
    if (tid == 0) {
        int pre = ntiles < STAGES ? ntiles : STAGES;
        for (int t = 0; t < pre; t++) {
            int t0 = row0 + t * TILE_ROWS;
            int rows = min(TILE_ROWS, row1 - t0);
            unsigned bytes = (unsigned)rows * (C * 4);
            mbar_expect_tx(mb[t], bytes);
            bulk_ld(smem_u32(s_buf + (size_t)t * TILE_F4),
                    x + (size_t)t0 * C, bytes, mb[t]);
        }
    }

    float4 accA = make_float4(0.f, 0.f, 0.f, 0.f);
    float4 accB = make_float4(0.f, 0.f, 0.f, 0.f);
    int cur_b = -1;

    for (int t = 0; t < ntiles; t++) {
        int stage  = t % STAGES;
        unsigned parity = (unsigned)((t / STAGES) & 1);
        mbar_wait(mb[stage], parity);

        int t0 = row0 + t * TILE_ROWS;
        int rows_here = min(TILE_ROWS, row1 - t0);
        const float4* tile = s_buf + (size_t)stage * TILE_F4;
        int base = warp * 8;   // warp owns 8 contiguous rows of the tile

        #pragma unroll
        for (int i = 0; i < 8; i++) {
            int local = base + i;
            if (local < rows_here) {
                int r = t0 + local;
                int b = bidx[r];                       // broadcast, cached
                if (b != cur_b) {                      // rare: segment change
                    if (cur_b >= 0) {
                        float* dst = &g_sums[cur_b][lane * 4];
                        atomicAdd(dst + 0, accA.x + accB.x);
                        atomicAdd(dst + 1, accA.y + accB.y);
                        atomicAdd(dst + 2, accA.z + accB.z);
                        atomicAdd(dst + 3, accA.w + accB.w);
                    }
                    cur_b = b;
                    accA = make_float4(0.f, 0.f, 0.f, 0.f);
                    accB = make_float4(0.f, 0.f, 0.f, 0.f);
                }
                float4 v = tile[local * CV + lane];    // conflict-free LDS.128
                if (i & 1) { accB.x += v.x; accB.y += v.y; accB.z += v.z; accB.w += v.w; }
                else       { accA.x += v.x; accA.y += v.y; accA.z += v.z; accA.w += v.w; }
            }
        }
        __syncthreads();   // everyone done with this buffer
        if (tid == 0 && t + STAGES < ntiles) {
            int tn = t + STAGES;
            int t0n = row0 + tn * TILE_ROWS;
            int rows = min(TILE_ROWS, row1 - t0n);
            unsigned bytes = (unsigned)rows * (C * 4);
            mbar_expect_tx(mb[stage], bytes);
            bulk_ld(smem_u32(s_buf + (size_t)stage * TILE_F4),
                    x + (size_t)t0n * C, bytes, mb[stage]);
        }
    }

    if (cur_b >= 0) {
        float* dst = &g_sums[cur_b][lane * 4];
        atomicAdd(dst + 0, accA.x + accB.x);
        atomicAdd(dst + 1, accA.y + accB.y);
        atomicAdd(dst + 2, accA.z + accB.z);
        atomicAdd(dst + 3, accA.w + accB.w);
    }
}

// ---------------------------------------------------------------------------
// 2) tiny MLP: 256 threads, weights cooperatively preloaded (vectorized) so
//    GMEM latency is paid once, not 128x serially. Re-zeroes accumulators.
// ---------------------------------------------------------------------------
__global__ __launch_bounds__(256) void mlp_kernel(
    const float* __restrict__ W1, const float* __restrict__ b1,
    const float* __restrict__ W2, const float* __restrict__ b2)
{
    __shared__ float sW1[C * HID];     // 1024
    __shared__ float sW2[HID * C];     // 1024
    __shared__ float s_b1[HID];
    __shared__ float s_b2[C];
    __shared__ float s_mean[NB][C];    // 2048
    __shared__ float s_h[NB][HID];     // 128

    int t = threadIdx.x;  // 0..255

    // batched, vectorized preloads (all independent -> one latency exposure)
    for (int i = t; i < (C * HID) / 4; i += 256) {
        ((float4*)sW1)[i] = ((const float4*)W1)[i];
        ((float4*)sW2)[i] = ((const float4*)W2)[i];
    }
    if (t < HID) s_b1[t] = b1[t];
    if (t < C)   s_b2[t] = b2[t];
    for (int i = t; i < NB * C; i += 256) {
        int b = i / C;
        float cn = fmaxf(g_counts[b], 1.0f);
        ((float*)s_mean)[i] = ((const float*)g_sums)[i] / cn;
    }
    __syncthreads();

    // reset accumulators for the next invocation
    for (int i = t; i < NB * C; i += 256) ((float*)g_sums)[i] = 0.0f;
    if (t < NB) g_counts[t] = 0.0f;

    if (t < NB * HID) {                // 128 outputs: h[b][j]
        int b = t / HID, j = t % HID;
        float acc = s_b1[j];
        #pragma unroll 8
        for (int c = 0; c < C; c++) acc += s_mean[b][c] * sW1[c * HID + j];
        s_h[b][j] = fmaxf(acc, 0.0f);
    }
    __syncthreads();

    if (t < C) {                       // gate column c = t
        int c = t;
        float w2c[HID];
        #pragma unroll
        for (int j = 0; j < HID; j++) w2c[j] = sW2[j * C + c];
        float bias = s_b2[c];
        for (int b = 0; b < NB; b++) {
            float acc = bias;
            #pragma unroll
            for (int j = 0; j < HID; j++) acc += s_h[b][j] * w2c[j];
            g_gate[b][c] = 1.0f / (1.0f + expf(-acc));
        }
    }
}

// ---------------------------------------------------------------------------
// 3) apply gate (measured 78.8us, at HBM ceiling): grid-stride ascending,
//    plain loads/stores, x2 unroll with front-batched loads.
// ---------------------------------------------------------------------------
__global__ __launch_bounds__(256) void apply_kernel(
    const float4* __restrict__ x, const int* __restrict__ bidx,
    float4* __restrict__ out, int n)
{
    __shared__ float4 s_gate[NB][CV];  // 8 KB
    for (int i = threadIdx.x; i < NB * CV; i += blockDim.x)
        ((float4*)s_gate)[i] = ((const float4*)g_gate)[i];
    __syncthreads();

    int lane = threadIdx.x & 31;
    int gwarp = (blockIdx.x * blockDim.x + threadIdx.x) >> 5;
    int nwarps = (gridDim.x * blockDim.x) >> 5;

    int r = gwarp;
    for (; r + nwarps < n; r += 2 * nwarps) {
        int r2 = r + nwarps;
        int b0 = bidx[r];
        int b1 = bidx[r2];
        float4 v0 = x[(size_t)r  * CV + lane];
        float4 v1 = x[(size_t)r2 * CV + lane];
        float4 g0 = s_gate[b0][lane];
        float4 g1 = s_gate[b1][lane];
        v0.x *= g0.x; v0.y *= g0.y; v0.z *= g0.z; v0.w *= g0.w;
        v1.x *= g1.x; v1.y *= g1.y; v1.z *= g1.z; v1.w *= g1.w;
        out[(size_t)r  * CV + lane] = v0;
        out[(size_t)r2 * CV + lane] = v1;
    }
    if (r < n) {
        int b = bidx[r];
        float4 v = x[(size_t)r * CV + lane];
        float4 g = s_gate[b][lane];
        v.x *= g.x; v.y *= g.y; v.z *= g.z; v.w *= g.w;
        out[(size_t)r * CV + lane] = v;
    }
}

// ---------------------------------------------------------------------------
extern "C" void kernel_launch(void* const* d_in, const int* in_sizes, int n_in,
                              void* d_out, int out_size)
{
    const float* x    = (const float*)d_in[0];
    const int*   bidx = (const int*)d_in[1];
    const float* W1   = (const float*)d_in[2];
    const float* b1   = (const float*)d_in[3];
    const float* W2   = (const float*)d_in[4];
    const float* b2   = (const float*)d_in[5];
    float* out = (float*)d_out;

    int n = in_sizes[1];  // number of rows (batch_idx has N entries)
    int rows_per_block = (n + RED_BLOCKS - 1) / RED_BLOCKS;

    // idempotent; host-side attr set (not an allocation, capture-safe)
    static int attr_done = 0;
    if (!attr_done) {
        cudaFuncSetAttribute(reduce_kernel,
                             cudaFuncAttributeMaxDynamicSharedMemorySize, RED_SMEM);
        attr_done = 1;
    }

    reduce_kernel<<<RED_BLOCKS, 256, RED_SMEM>>>(x, bidx, n, rows_per_block);
    mlp_kernel<<<1, 256>>>(W1, b1, W2, b2);
    apply_kernel<<<APPLY_BLOCKS, 256>>>((const float4*)x, bidx, (float4*)out, n);
}